// round 1
// baseline (speedup 1.0000x reference)
#include <cuda_runtime.h>

#define NN   100000
#define DHD  64
#define DINF 128

// Scratch (static device globals — no allocation allowed)
__device__ float g_deg[NN];
__device__ float g_dinv[NN];
__device__ float g_h[NN * DHD];     // linear-transform output (layer input to scatter)
__device__ float g_agg[NN * DHD];   // aggregation accumulator
__device__ float g_z[NN * DHD];     // layer-1 activation output

// ---------------------------------------------------------------------------
// deg init: every node has a self-loop => start at 1.0
__global__ void k_init_deg(float* __restrict__ deg, int n) {
    int i = blockIdx.x * blockDim.x + threadIdx.x;
    if (i < n) deg[i] = 1.0f;
}

// count in-degree over edges
__global__ void k_count_deg(const int* __restrict__ dst, float* __restrict__ deg, int e) {
    int i = blockIdx.x * blockDim.x + threadIdx.x;
    if (i < e) atomicAdd(&deg[dst[i]], 1.0f);
}

__global__ void k_dinv(const float* __restrict__ deg, float* __restrict__ dinv, int n) {
    int i = blockIdx.x * blockDim.x + threadIdx.x;
    if (i < n) dinv[i] = rsqrtf(deg[i]);
}

// ---------------------------------------------------------------------------
// GEMM: H[n,64] = X[n,K] @ W[K,64].  W staged in smem as float4 rows.
// 256 threads/block, 16 rows/block; 16 lanes per row, each lane owns 4 cols.
template <int K>
__global__ void k_gemm(const float* __restrict__ X, const float* __restrict__ W,
                       float* __restrict__ H, int n) {
    __shared__ float4 Wsh[K * 16];
    for (int idx = threadIdx.x; idx < K * 16; idx += 256)
        Wsh[idx] = ((const float4*)W)[idx];
    __syncthreads();

    int row = blockIdx.x * 16 + (threadIdx.x >> 4);
    int sub = threadIdx.x & 15;
    if (row >= n) return;

    const float4* x4 = (const float4*)(X + (size_t)row * K);
    float4 acc = make_float4(0.f, 0.f, 0.f, 0.f);

#pragma unroll
    for (int k4 = 0; k4 < K / 4; ++k4) {
        float4 xv = x4[k4];  // broadcast across the 16 lanes of this row
        float4 w;
        w = Wsh[(4 * k4 + 0) * 16 + sub];
        acc.x += xv.x * w.x; acc.y += xv.x * w.y; acc.z += xv.x * w.z; acc.w += xv.x * w.w;
        w = Wsh[(4 * k4 + 1) * 16 + sub];
        acc.x += xv.y * w.x; acc.y += xv.y * w.y; acc.z += xv.y * w.z; acc.w += xv.y * w.w;
        w = Wsh[(4 * k4 + 2) * 16 + sub];
        acc.x += xv.z * w.x; acc.y += xv.z * w.y; acc.z += xv.z * w.z; acc.w += xv.z * w.w;
        w = Wsh[(4 * k4 + 3) * 16 + sub];
        acc.x += xv.w * w.x; acc.y += xv.w * w.y; acc.z += xv.w * w.z; acc.w += xv.w * w.w;
    }
    ((float4*)H)[(size_t)row * 16 + sub] = acc;
}

// ---------------------------------------------------------------------------
// Self-loop init: agg[i][:] = h[i][:] * dinv[i]^2   (vectorized, i over n*16 float4)
__global__ void k_selfinit(const float4* __restrict__ h, const float* __restrict__ dinv,
                           float4* __restrict__ agg, int n16) {
    int i = blockIdx.x * blockDim.x + threadIdx.x;
    if (i >= n16) return;
    int row = i >> 4;
    float dv = dinv[row];
    float s = dv * dv;
    float4 v = h[i];
    v.x *= s; v.y *= s; v.z *= s; v.w *= s;
    agg[i] = v;
}

// ---------------------------------------------------------------------------
// Edge scatter: agg[dst] += h[src] * (dinv[src]*dinv[dst])
// 16 lanes per edge, one red.global.add.v4.f32 (16B) per lane.
__global__ void k_scatter(const float* __restrict__ h, const int* __restrict__ src,
                          const int* __restrict__ dst, const float* __restrict__ dinv,
                          float* __restrict__ agg, int e) {
    int t = blockIdx.x * blockDim.x + threadIdx.x;
    int ed = t >> 4;
    if (ed >= e) return;
    int lane = t & 15;

    int s = __ldg(src + ed);
    int d = __ldg(dst + ed);
    float nrm = __ldg(dinv + s) * __ldg(dinv + d);

    float4 v = ((const float4*)h)[(size_t)s * 16 + lane];
    v.x *= nrm; v.y *= nrm; v.z *= nrm; v.w *= nrm;

    float* p = agg + ((size_t)d * DHD + lane * 4);
    asm volatile("red.global.add.v4.f32 [%0], {%1, %2, %3, %4};"
                 :: "l"(p), "f"(v.x), "f"(v.y), "f"(v.z), "f"(v.w)
                 : "memory");
}

// ---------------------------------------------------------------------------
// Epilogue: out = prelu(agg + b)  (per-channel alpha), vectorized
__global__ void k_prelu(const float4* __restrict__ agg, const float* __restrict__ b,
                        const float* __restrict__ alpha, float4* __restrict__ out, int n16) {
    int i = blockIdx.x * blockDim.x + threadIdx.x;
    if (i >= n16) return;
    int j4 = i & 15;
    float4 a  = agg[i];
    float4 bb = ((const float4*)b)[j4];
    float4 al = ((const float4*)alpha)[j4];
    float4 r;
    r.x = a.x + bb.x; r.x = (r.x >= 0.f) ? r.x : al.x * r.x;
    r.y = a.y + bb.y; r.y = (r.y >= 0.f) ? r.y : al.y * r.y;
    r.z = a.z + bb.z; r.z = (r.z >= 0.f) ? r.z : al.z * r.z;
    r.w = a.w + bb.w; r.w = (r.w >= 0.f) ? r.w : al.w * r.w;
    out[i] = r;
}

// ---------------------------------------------------------------------------
extern "C" void kernel_launch(void* const* d_in, const int* in_sizes, int n_in,
                              void* d_out, int out_size) {
    const float* x     = (const float*)d_in[0];
    const int*   ei    = (const int*)d_in[1];
    const float* W1    = (const float*)d_in[2];
    const float* b1    = (const float*)d_in[3];
    const float* W2    = (const float*)d_in[4];
    const float* b2    = (const float*)d_in[5];
    const float* alpha = (const float*)d_in[6];
    float*       out   = (float*)d_out;

    int n = in_sizes[0] / DINF;   // 100000
    int e = in_sizes[1] / 2;      // 1600000
    const int* src = ei;
    const int* dst = ei + e;

    void* p;
    cudaGetSymbolAddress(&p, g_deg);  float* deg  = (float*)p;
    cudaGetSymbolAddress(&p, g_dinv); float* dinv = (float*)p;
    cudaGetSymbolAddress(&p, g_h);    float* h    = (float*)p;
    cudaGetSymbolAddress(&p, g_agg);  float* agg  = (float*)p;
    cudaGetSymbolAddress(&p, g_z);    float* z    = (float*)p;

    const int T = 256;
    int n16 = n * 16;  // number of float4 elements per [n,64] tensor

    // degrees + normalization
    k_init_deg<<<(n + T - 1) / T, T>>>(deg, n);
    k_count_deg<<<(e + T - 1) / T, T>>>(dst, deg, e);
    k_dinv<<<(n + T - 1) / T, T>>>(deg, dinv, n);

    // ---- layer 1 ----
    k_gemm<DINF><<<(n + 15) / 16, T>>>(x, W1, h, n);
    k_selfinit<<<(n16 + T - 1) / T, T>>>((const float4*)h, dinv, (float4*)agg, n16);
    k_scatter<<<((e * 16) + T - 1) / T, T>>>(h, src, dst, dinv, agg, e);
    k_prelu<<<(n16 + T - 1) / T, T>>>((const float4*)agg, b1, alpha, (float4*)z, n16);

    // ---- layer 2 ----
    k_gemm<DHD><<<(n + 15) / 16, T>>>(z, W2, h, n);
    k_selfinit<<<(n16 + T - 1) / T, T>>>((const float4*)h, dinv, (float4*)agg, n16);
    k_scatter<<<((e * 16) + T - 1) / T, T>>>(h, src, dst, dinv, agg, e);
    k_prelu<<<(n16 + T - 1) / T, T>>>((const float4*)agg, b2, alpha, (float4*)out, n16);
}